// round 1
// baseline (speedup 1.0000x reference)
#include <cuda_runtime.h>
#include <math.h>

// ---------------- scratch (no allocations allowed) ----------------
#define N_LEAVES_MAX 100000
#define RB 512               // reduce blocks for the pair kernel

__device__ float  g_dleaf[N_LEAVES_MAX];
__device__ float4 g_part[RB];   // (m, sum_exp, sum_sims_exp, sum_sims)

// ---------------- Kernel A: per-leaf hyperbolic distance ----------------
// One warp per leaf. e1 (normalized anchor) recomputed per block in shared.
__global__ void leaf_dist_kernel(const int* __restrict__ lca,
                                 const float* __restrict__ emb,
                                 const float* __restrict__ leaves,
                                 const float* __restrict__ scale,
                                 int n_leaves)
{
    __shared__ __align__(16) float s_e1[128];
    __shared__ float s_red[128];
    __shared__ float s_inv;   // 1 / (1 - |e1|^2)

    const int t = threadIdx.x;

    // --- build e1 = emb[lca] / max(||.||,1e-12) * clip(scale,0.01,0.999) ---
    const float* row = emb + (long long)lca[0] * 128;
    float w = 0.0f;
    if (t < 128) { w = row[t]; s_red[t] = w * w; }
    __syncthreads();
    for (int off = 64; off > 0; off >>= 1) {
        if (t < off) s_red[t] += s_red[t + off];
        __syncthreads();
    }
    const float norm2  = s_red[0];
    const float s      = fminf(fmaxf(scale[0], 0.01f), 1.0f - 0.001f);
    const float factor = s / fmaxf(sqrtf(norm2), 1e-12f);
    if (t < 128) s_e1[t] = w * factor;
    if (t == 0) {
        float nx = factor * factor * norm2;
        s_inv = 1.0f / (1.0f - nx);
    }
    __syncthreads();

    // --- one warp per leaf, one float4 per lane (128 floats / leaf) ---
    const int lane    = t & 31;
    const int warp    = (blockIdx.x * blockDim.x + t) >> 5;
    const int n_warps = (gridDim.x * blockDim.x) >> 5;
    const float4 e = reinterpret_cast<const float4*>(s_e1)[lane];

    for (int leaf = warp; leaf < n_leaves; leaf += n_warps) {
        const float4 y = reinterpret_cast<const float4*>(leaves)[(size_t)leaf * 32 + lane];
        float dx = e.x - y.x, dy = e.y - y.y, dz = e.z - y.z, dw = e.w - y.w;
        float sq = dx * dx + dy * dy + dz * dz + dw * dw;
        float ny = y.x * y.x + y.y * y.y + y.z * y.z + y.w * y.w;
        #pragma unroll
        for (int o = 16; o > 0; o >>= 1) {
            sq += __shfl_down_sync(0xffffffffu, sq, o);
            ny += __shfl_down_sync(0xffffffffu, ny, o);
        }
        if (lane == 0) {
            float arg = 1.0f + 2.0f * sq * s_inv / (1.0f - ny);
            arg = fmaxf(arg, 1.0f + 1e-7f);
            g_dleaf[leaf] = acoshf(arg);
        }
    }
}

// combine two online-softmax states (order-fixed, deterministic)
__device__ __forceinline__ void comb(float& m, float& se, float& ss,
                                     float m2, float se2, float ss2)
{
    if (m2 > m) {
        float c = (m == -INFINITY) ? 0.0f : expf(m - m2);
        se = se * c + se2;
        ss = ss * c + ss2;
        m  = m2;
    } else {
        float c = (m2 == -INFINITY) ? 0.0f : expf(m2 - m);
        se += se2 * c;
        ss += ss2 * c;
    }
}

// ---------------- Kernel B: online softmax over 1M pairs ----------------
__global__ void pair_reduce_kernel(const int* __restrict__ l_idx,
                                   const int* __restrict__ r_idx,
                                   const float* __restrict__ sims,
                                   int n_pairs)
{
    const int t      = threadIdx.x;
    const int tid    = blockIdx.x * blockDim.x + t;
    const int stride = gridDim.x * blockDim.x;

    float m = -INFINITY, se = 0.0f, ss = 0.0f, ssum = 0.0f;

    for (int i = tid; i < n_pairs; i += stride) {
        float x  = (g_dleaf[l_idx[i]] + g_dleaf[r_idx[i]]) * 20.0f;  // d / 0.05
        float si = sims[i];
        ssum += si;
        if (x > m) {
            float c = expf(m - x);   // expf(-inf) == 0, handles first iter
            se = se * c + 1.0f;
            ss = ss * c + si;
            m  = x;
        } else {
            float e = expf(x - m);
            se += e;
            ss += si * e;
        }
    }

    __shared__ float sm[256], sse[256], sss[256], ssu[256];
    sm[t] = m; sse[t] = se; sss[t] = ss; ssu[t] = ssum;
    __syncthreads();
    for (int off = 128; off > 0; off >>= 1) {
        if (t < off) {
            comb(sm[t], sse[t], sss[t], sm[t + off], sse[t + off], sss[t + off]);
            ssu[t] += ssu[t + off];
        }
        __syncthreads();
    }
    if (t == 0)
        g_part[blockIdx.x] = make_float4(sm[0], sse[0], sss[0], ssu[0]);
}

// ---------------- Kernel C: finalize ----------------
__global__ void finalize_kernel(float* __restrict__ out)
{
    const int t = threadIdx.x;   // 256 threads
    float m = -INFINITY, se = 0.0f, ss = 0.0f, ssum = 0.0f;
    for (int i = t; i < RB; i += 256) {
        float4 p = g_part[i];
        comb(m, se, ss, p.x, p.y, p.z);
        ssum += p.w;
    }
    __shared__ float sm[256], sse[256], sss[256], ssu[256];
    sm[t] = m; sse[t] = se; sss[t] = ss; ssu[t] = ssum;
    __syncthreads();
    for (int off = 128; off > 0; off >>= 1) {
        if (t < off) {
            comb(sm[t], sse[t], sss[t], sm[t + off], sse[t + off], sss[t + off]);
            ssu[t] += ssu[t + off];
        }
        __syncthreads();
    }
    if (t == 0)
        out[0] = ssu[0] - sss[0] / sse[0];   // sum(sims) - w_ord
}

// ---------------- launch ----------------
extern "C" void kernel_launch(void* const* d_in, const int* in_sizes, int n_in,
                              void* d_out, int out_size)
{
    const int*   lca    = (const int*)  d_in[0];
    const int*   l_idx  = (const int*)  d_in[1];
    const int*   r_idx  = (const int*)  d_in[2];
    const float* sims   = (const float*)d_in[3];
    const float* emb    = (const float*)d_in[4];
    const float* leaves = (const float*)d_in[5];
    const float* scale  = (const float*)d_in[6];

    const int n_pairs  = in_sizes[1];
    const int n_leaves = in_sizes[5] / 128;

    const int blocksA = (n_leaves + 7) / 8;   // 8 warps/block, one leaf per warp
    leaf_dist_kernel<<<blocksA, 256>>>(lca, emb, leaves, scale, n_leaves);
    pair_reduce_kernel<<<RB, 256>>>(l_idx, r_idx, sims, n_pairs);
    finalize_kernel<<<1, 256>>>((float*)d_out);
}

// round 3
// speedup vs baseline: 1.9518x; 1.9518x over previous
#include <cuda_runtime.h>
#include <cuda_fp16.h>
#include <cstdint>
#include <math.h>

// ---------------- scratch (no allocations allowed) ----------------
#define N_LEAVES_MAX 100000
#define MAXB 256

__device__ __half  g_dleaf[N_LEAVES_MAX + 16];  // padded so 16B chunked reads stay in-bounds
__device__ int     g_maxint;                    // max d as ordered int (positive floats)
__device__ float4  g_part[MAXB];                // (sum_exp, sum_sims_exp, sum_sims, -)

// ---------------- helpers ----------------
__device__ __forceinline__ void cp_async16(unsigned int dst_smem, const void* src) {
    asm volatile("cp.async.cg.shared.global [%0], [%1], 16;" :: "r"(dst_smem), "l"(src));
}

#define TILE_A 128
#define ROWF   132   // padded floats per row: (4t+4k)%32 -> 4-phase minimum for LDS.128

// ---------------- Kernel A: per-leaf hyperbolic distance ----------------
// Block = 128 threads, tile = 128 leaves staged in smem; thread-per-leaf compute.
__global__ __launch_bounds__(128) void leaf_dist_kernel(
        const int* __restrict__ lca,
        const float* __restrict__ emb,
        const float* __restrict__ leaves,
        const float* __restrict__ scale,
        int n_leaves)
{
    extern __shared__ float sm[];                 // [TILE_A*ROWF] y-tile, then [128] e
    float* s_y = sm;
    float* s_e = sm + TILE_A * ROWF;
    __shared__ float s_red[128];
    __shared__ float s_nx, s_inv;

    const int t     = threadIdx.x;
    const int leaf0 = blockIdx.x * TILE_A;
    const int valid = min(TILE_A, n_leaves - leaf0);

    // --- stage tile: 4096 float4s, coalesced, async ---
    const float4* src = reinterpret_cast<const float4*>(leaves + (size_t)leaf0 * 128);
    unsigned int sbase = (unsigned int)__cvta_generic_to_shared(s_y);
    #pragma unroll
    for (int j = 0; j < 32; j++) {
        int f   = t + j * 128;          // float4 index within tile
        int row = f >> 5, col = f & 31;
        if (row < valid)
            cp_async16(sbase + row * (ROWF * 4) + col * 16, src + f);
    }
    asm volatile("cp.async.commit_group;");

    // --- build e1 = emb[lca]/max(||.||,1e-12) * clip(scale) while loads fly ---
    const float* erow = emb + (long long)lca[0] * 128;
    float w = erow[t];
    s_red[t] = w * w;
    __syncthreads();
    for (int off = 64; off > 0; off >>= 1) {
        if (t < off) s_red[t] += s_red[t + off];
        __syncthreads();
    }
    if (t == 0) {
        float norm2  = s_red[0];
        float s      = fminf(fmaxf(scale[0], 0.01f), 1.0f - 0.001f);
        float factor = s / fmaxf(sqrtf(norm2), 1e-12f);
        float nx     = factor * factor * norm2;
        s_nx  = nx;
        s_inv = 1.0f / (1.0f - nx);
        s_red[0] = factor;
    }
    __syncthreads();
    s_e[t] = w * s_red[0];

    asm volatile("cp.async.wait_group 0;");
    __syncthreads();

    // --- thread-per-leaf: dot = e.y, ny = |y|^2 ---
    float d = 0.0f;
    if (t < valid) {
        const float4* yr = reinterpret_cast<const float4*>(s_y + t * ROWF);
        const float4* er = reinterpret_cast<const float4*>(s_e);
        float dot = 0.0f, ny = 0.0f;
        #pragma unroll
        for (int k = 0; k < 32; k++) {
            float4 y = yr[k];
            float4 e = er[k];          // broadcast read
            dot = fmaf(e.x, y.x, fmaf(e.y, y.y, fmaf(e.z, y.z, fmaf(e.w, y.w, dot))));
            ny  = fmaf(y.x, y.x, fmaf(y.y, y.y, fmaf(y.z, y.z, fmaf(y.w, y.w, ny))));
        }
        float sq  = s_nx - 2.0f * dot + ny;         // |e-y|^2
        float arg = 1.0f + 2.0f * sq * s_inv / (1.0f - ny);
        arg = fmaxf(arg, 1.0f + 1e-7f);
        d   = acoshf(arg);
        g_dleaf[leaf0 + t] = __float2half(d);
    }

    // --- block max -> global atomicMax (order-independent, deterministic) ---
    s_red[t] = d;
    __syncthreads();
    for (int off = 64; off > 0; off >>= 1) {
        if (t < off) s_red[t] = fmaxf(s_red[t], s_red[t + off]);
        __syncthreads();
    }
    if (t == 0) atomicMax(&g_maxint, __float_as_int(s_red[0]));
}

// ---------------- Kernel B: branchless softmax partial sums ----------------
// One block per SM; whole fp16 d-table staged into shared, gathers are LDS.
__global__ __launch_bounds__(1024) void pair_reduce_kernel(
        const int* __restrict__ l_idx,
        const int* __restrict__ r_idx,
        const float* __restrict__ sims,
        int n_pairs, int n_leaves)
{
    extern __shared__ __half s_tab[];
    __shared__ float r_se[1024], r_ss[1024], r_su[1024];

    const int t = threadIdx.x;

    // stage table (written by kernel A, L2-resident) into smem
    unsigned int sb = (unsigned int)__cvta_generic_to_shared(s_tab);
    int nchunks = (n_leaves * 2 + 15) >> 4;
    const char* gsrc = reinterpret_cast<const char*>(g_dleaf);
    for (int c = t; c < nchunks; c += blockDim.x)
        cp_async16(sb + c * 16, gsrc + c * 16);
    asm volatile("cp.async.commit_group;");

    const float M = 40.0f * __int_as_float(g_maxint);   // upper bound on x = 20(dl+dr)

    asm volatile("cp.async.wait_group 0;");
    __syncthreads();

    float se = 0.0f, ss = 0.0f, su = 0.0f;
    const int stride = gridDim.x * blockDim.x;
    for (int i = blockIdx.x * blockDim.x + t; i < n_pairs; i += stride) {
        float dl = __half2float(s_tab[l_idx[i]]);
        float dr = __half2float(s_tab[r_idx[i]]);
        float si = sims[i];
        float e  = __expf(fmaf(20.0f, dl + dr, -M));
        se += e;
        ss = fmaf(si, e, ss);
        su += si;
    }

    r_se[t] = se; r_ss[t] = ss; r_su[t] = su;
    __syncthreads();
    for (int off = 512; off > 0; off >>= 1) {
        if (t < off) {
            r_se[t] += r_se[t + off];
            r_ss[t] += r_ss[t + off];
            r_su[t] += r_su[t + off];
        }
        __syncthreads();
    }
    if (t == 0) g_part[blockIdx.x] = make_float4(r_se[0], r_ss[0], r_su[0], 0.0f);
}

// ---------------- Kernel C: finalize ----------------
__global__ void finalize_kernel(float* __restrict__ out, int nb)
{
    __shared__ float r_se[128], r_ss[128], r_su[128];
    const int t = threadIdx.x;
    float se = 0.0f, ss = 0.0f, su = 0.0f;
    for (int i = t; i < nb; i += 128) {
        float4 p = g_part[i];
        se += p.x; ss += p.y; su += p.z;
    }
    r_se[t] = se; r_ss[t] = ss; r_su[t] = su;
    __syncthreads();
    for (int off = 64; off > 0; off >>= 1) {
        if (t < off) {
            r_se[t] += r_se[t + off];
            r_ss[t] += r_ss[t + off];
            r_su[t] += r_su[t + off];
        }
        __syncthreads();
    }
    if (t == 0) out[0] = r_su[0] - r_ss[0] / r_se[0];   // sum(sims) - w_ord
}

// ---------------- launch ----------------
extern "C" void kernel_launch(void* const* d_in, const int* in_sizes, int n_in,
                              void* d_out, int out_size)
{
    const int*   lca    = (const int*)  d_in[0];
    const int*   l_idx  = (const int*)  d_in[1];
    const int*   r_idx  = (const int*)  d_in[2];
    const float* sims   = (const float*)d_in[3];
    const float* emb    = (const float*)d_in[4];
    const float* leaves = (const float*)d_in[5];
    const float* scale  = (const float*)d_in[6];

    const int n_pairs  = in_sizes[1];
    const int n_leaves = in_sizes[5] / 128;

    // attribute setup (host-side, capture-safe)
    const int smemA = (TILE_A * ROWF + 128) * 4;                 // 68096 B
    const int smemB = ((n_leaves * 2 + 15) & ~15);               // fp16 table bytes
    cudaFuncSetAttribute(leaf_dist_kernel,
                         cudaFuncAttributeMaxDynamicSharedMemorySize, smemA);
    cudaFuncSetAttribute(pair_reduce_kernel,
                         cudaFuncAttributeMaxDynamicSharedMemorySize,
                         (N_LEAVES_MAX * 2 + 64));

    int sm_count = 0;
    cudaDeviceGetAttribute(&sm_count, cudaDevAttrMultiProcessorCount, 0);
    if (sm_count <= 0 || sm_count > MAXB) sm_count = 148;

    const int blocksA = (n_leaves + TILE_A - 1) / TILE_A;
    leaf_dist_kernel<<<blocksA, 128, smemA>>>(lca, emb, leaves, scale, n_leaves);
    pair_reduce_kernel<<<sm_count, 1024, smemB>>>(l_idx, r_idx, sims, n_pairs, n_leaves);
    finalize_kernel<<<1, 128>>>((float*)d_out, sm_count);
}